// round 1
// baseline (speedup 1.0000x reference)
#include <cuda_runtime.h>
#include <math.h>

// Problem constants (fixed by the dataset)
#define B_ 8
#define N_ 2048
#define D_ 512
#define E_ 512

// SGEMM tiling
#define BM 128
#define BN 128
#define BK 8
#define TM 8
#define TN 8

// Scratch for projected q/k/v: 3 x 8*2048*512 fp32 = 100.7 MB (static device
// arrays — allocation-guard safe).
__device__ float g_qp[(long)B_ * N_ * E_];
__device__ float g_kp[(long)B_ * N_ * E_];
__device__ float g_vp[(long)B_ * N_ * E_];

// ---------------------------------------------------------------------------
// C[M,N] = alpha * A[M,K] @ B[N,K]^T   (both A and B row-major, K contiguous)
// Batched via blockIdx.z with element strides sA/sB/sC.
// Requires M%BM==0, N%BN==0, K%BK==0 (true for all our shapes).
// ---------------------------------------------------------------------------
__global__ __launch_bounds__(256) void gemm_nt(
    const float* __restrict__ A, const float* __restrict__ B,
    float* __restrict__ C,
    int M, int N, int K,
    long sA, long sB, long sC, float alpha)
{
    __shared__ float As[BK][BM];
    __shared__ float Bs[BK][BN];

    A += (long)blockIdx.z * sA;
    B += (long)blockIdx.z * sB;
    C += (long)blockIdx.z * sC;

    const int m0 = blockIdx.y * BM;
    const int n0 = blockIdx.x * BN;
    const int t  = threadIdx.x;
    const int tx = t & 15;        // 0..15 -> column group
    const int ty = t >> 4;        // 0..15 -> row group

    // Global->shared load mapping: 256 threads, each loads one float4 from A
    // and one from B per k-step. 128 rows x 2 float4 segments.
    const int lrow = t >> 1;          // 0..127
    const int lseg = (t & 1) * 4;     // 0 or 4

    float acc[TM][TN];
    #pragma unroll
    for (int i = 0; i < TM; i++)
        #pragma unroll
        for (int j = 0; j < TN; j++) acc[i][j] = 0.0f;

    const float* Aptr = A + (long)(m0 + lrow) * K + lseg;
    const float* Bptr = B + (long)(n0 + lrow) * K + lseg;

    for (int k0 = 0; k0 < K; k0 += BK) {
        float4 av = *(const float4*)(Aptr + k0);
        float4 bv = *(const float4*)(Bptr + k0);
        As[lseg + 0][lrow] = av.x;
        As[lseg + 1][lrow] = av.y;
        As[lseg + 2][lrow] = av.z;
        As[lseg + 3][lrow] = av.w;
        Bs[lseg + 0][lrow] = bv.x;
        Bs[lseg + 1][lrow] = bv.y;
        Bs[lseg + 2][lrow] = bv.z;
        Bs[lseg + 3][lrow] = bv.w;
        __syncthreads();

        #pragma unroll
        for (int kk = 0; kk < BK; kk++) {
            float ra[TM], rb[TN];
            #pragma unroll
            for (int i = 0; i < TM; i++) ra[i] = As[kk][ty * TM + i];
            #pragma unroll
            for (int j = 0; j < TN; j++) rb[j] = Bs[kk][tx * TN + j];
            #pragma unroll
            for (int i = 0; i < TM; i++)
                #pragma unroll
                for (int j = 0; j < TN; j++)
                    acc[i][j] = fmaf(ra[i], rb[j], acc[i][j]);
        }
        __syncthreads();
    }

    #pragma unroll
    for (int i = 0; i < TM; i++) {
        float* crow = C + (long)(m0 + ty * TM + i) * N + n0 + tx * TN;
        #pragma unroll
        for (int j = 0; j < TN; j += 4) {
            float4 v;
            v.x = acc[i][j + 0] * alpha;
            v.y = acc[i][j + 1] * alpha;
            v.z = acc[i][j + 2] * alpha;
            v.w = acc[i][j + 3] * alpha;
            *(float4*)(crow + j) = v;
        }
    }
}

// ---------------------------------------------------------------------------
// C[M,N] = alpha * A[M,K] @ B[K,N]   (A row-major K-contig, B row-major N-contig)
// ---------------------------------------------------------------------------
__global__ __launch_bounds__(256) void gemm_nn(
    const float* __restrict__ A, const float* __restrict__ B,
    float* __restrict__ C,
    int M, int N, int K,
    long sA, long sB, long sC, float alpha)
{
    __shared__ float As[BK][BM];
    __shared__ float Bs[BK][BN];

    A += (long)blockIdx.z * sA;
    B += (long)blockIdx.z * sB;
    C += (long)blockIdx.z * sC;

    const int m0 = blockIdx.y * BM;
    const int n0 = blockIdx.x * BN;
    const int t  = threadIdx.x;
    const int tx = t & 15;
    const int ty = t >> 4;

    // A load mapping (same as NT)
    const int larow = t >> 1;
    const int laseg = (t & 1) * 4;
    // B load mapping: tile is BK rows x BN cols of B; 8 rows x 32 float4 cols.
    const int lbrow = t >> 5;          // 0..7
    const int lbcol = (t & 31) * 4;    // 0..124 step 4

    float acc[TM][TN];
    #pragma unroll
    for (int i = 0; i < TM; i++)
        #pragma unroll
        for (int j = 0; j < TN; j++) acc[i][j] = 0.0f;

    const float* Aptr = A + (long)(m0 + larow) * K + laseg;

    for (int k0 = 0; k0 < K; k0 += BK) {
        float4 av = *(const float4*)(Aptr + k0);
        As[laseg + 0][larow] = av.x;
        As[laseg + 1][larow] = av.y;
        As[laseg + 2][larow] = av.z;
        As[laseg + 3][larow] = av.w;
        float4 bv = *(const float4*)(B + (long)(k0 + lbrow) * N + n0 + lbcol);
        *(float4*)&Bs[lbrow][lbcol] = bv;
        __syncthreads();

        #pragma unroll
        for (int kk = 0; kk < BK; kk++) {
            float ra[TM], rb[TN];
            #pragma unroll
            for (int i = 0; i < TM; i++) ra[i] = As[kk][ty * TM + i];
            #pragma unroll
            for (int j = 0; j < TN; j++) rb[j] = Bs[kk][tx * TN + j];
            #pragma unroll
            for (int i = 0; i < TM; i++)
                #pragma unroll
                for (int j = 0; j < TN; j++)
                    acc[i][j] = fmaf(ra[i], rb[j], acc[i][j]);
        }
        __syncthreads();
    }

    #pragma unroll
    for (int i = 0; i < TM; i++) {
        float* crow = C + (long)(m0 + ty * TM + i) * N + n0 + tx * TN;
        #pragma unroll
        for (int j = 0; j < TN; j += 4) {
            float4 v;
            v.x = acc[i][j + 0] * alpha;
            v.y = acc[i][j + 1] * alpha;
            v.z = acc[i][j + 2] * alpha;
            v.w = acc[i][j + 3] * alpha;
            *(float4*)(crow + j) = v;
        }
    }
}

// ---------------------------------------------------------------------------
// In-place row softmax over rows of length ncols. One block per row.
// ---------------------------------------------------------------------------
__global__ __launch_bounds__(256) void softmax_rows(float* __restrict__ attn, int ncols)
{
    float* p = attn + (long)blockIdx.x * ncols;
    const int t = threadIdx.x;
    __shared__ float red[256];

    float vmax = -INFINITY;
    for (int c = t; c < ncols; c += 256) vmax = fmaxf(vmax, p[c]);
    red[t] = vmax;
    __syncthreads();
    for (int s = 128; s > 0; s >>= 1) {
        if (t < s) red[t] = fmaxf(red[t], red[t + s]);
        __syncthreads();
    }
    vmax = red[0];
    __syncthreads();

    float sum = 0.0f;
    for (int c = t; c < ncols; c += 256) {
        float e = expf(p[c] - vmax);
        p[c] = e;
        sum += e;
    }
    red[t] = sum;
    __syncthreads();
    for (int s = 128; s > 0; s >>= 1) {
        if (t < s) red[t] += red[t + s];
        __syncthreads();
    }
    float inv = 1.0f / red[0];
    __syncthreads();

    for (int c = t; c < ncols; c += 256) p[c] *= inv;
}

// ---------------------------------------------------------------------------
extern "C" void kernel_launch(void* const* d_in, const int* in_sizes, int n_in,
                              void* d_out, int out_size)
{
    const float* q  = (const float*)d_in[0];
    const float* k  = (const float*)d_in[1];
    const float* v  = (const float*)d_in[2];
    const float* Wq = (const float*)d_in[3];
    const float* Wk = (const float*)d_in[4];
    const float* Wv = (const float*)d_in[5];

    float* out  = (float*)d_out;                       // [B, N, E]
    float* attn = out + (long)B_ * N_ * E_;            // [B, N, N]

    float* qp; float* kp; float* vp;
    cudaGetSymbolAddress((void**)&qp, g_qp);
    cudaGetSymbolAddress((void**)&kp, g_kp);
    cudaGetSymbolAddress((void**)&vp, g_vp);

    const float c_eq  = rsqrtf((float)D_);   // EqualizedLinear 1/sqrt(fan_in)
    const float scale = rsqrtf((float)E_);   // attention 1/sqrt(e)

    // 1) Projections: [B*N, D] @ W^T -> [B*N, E], scaled by c_eq
    {
        dim3 grid(E_ / BN, (B_ * N_) / BM, 1);
        gemm_nt<<<grid, 256>>>(q, Wq, qp, B_ * N_, E_, D_, 0, 0, 0, c_eq);
        gemm_nt<<<grid, 256>>>(k, Wk, kp, B_ * N_, E_, D_, 0, 0, 0, c_eq);
        gemm_nt<<<grid, 256>>>(v, Wv, vp, B_ * N_, E_, D_, 0, 0, 0, c_eq);
    }

    // 2) dots = qp @ kp^T * scale, written straight into attn region
    {
        dim3 grid(N_ / BN, N_ / BM, B_);
        gemm_nt<<<grid, 256>>>(qp, kp, attn, N_, N_, E_,
                               (long)N_ * E_, (long)N_ * E_, (long)N_ * N_,
                               scale);
    }

    // 3) softmax rows (in place)
    softmax_rows<<<B_ * N_, 256>>>(attn, N_);

    // 4) out = attn @ vp
    {
        dim3 grid(E_ / BN, N_ / BM, B_);
        gemm_nn<<<grid, 256>>>(attn, vp, out, N_, E_, N_,
                               (long)N_ * N_, (long)N_ * E_, (long)N_ * E_,
                               1.0f);
    }
}

// round 3
// speedup vs baseline: 2.3251x; 2.3251x over previous
#include <cuda_runtime.h>
#include <cuda_fp16.h>
#include <cstdint>
#include <math.h>

// Problem constants
#define B_ 8
#define N_ 2048
#define D_ 512
#define E_ 512

static constexpr long QKV_ELEMS  = (long)B_ * N_ * D_;   // 8,388,608
static constexpr long W_ELEMS    = (long)E_ * D_;        // 262,144
static constexpr long ATTN_ELEMS = (long)B_ * N_ * N_;   // 33,554,432

// ---------------- scratch (static device arrays; allocation-guard safe) ----
__device__ __half g_qh[QKV_ELEMS],  g_ql[QKV_ELEMS];
__device__ __half g_kh[QKV_ELEMS],  g_kl[QKV_ELEMS];
__device__ __half g_vh[QKV_ELEMS],  g_vl[QKV_ELEMS];
__device__ __half g_Wqh[W_ELEMS],   g_Wql[W_ELEMS];
__device__ __half g_Wkh[W_ELEMS],   g_Wkl[W_ELEMS];
__device__ __half g_Wvh[W_ELEMS],   g_Wvl[W_ELEMS];
__device__ __half g_qph[QKV_ELEMS], g_qpl[QKV_ELEMS];
__device__ __half g_kph[QKV_ELEMS], g_kpl[QKV_ELEMS];
__device__ __half g_vpth[QKV_ELEMS], g_vptl[QKV_ELEMS];   // transposed [b][e][n]
__device__ __half g_ah[ATTN_ELEMS], g_al[ATTN_ELEMS];

// ---------------- PTX helpers ----------------------------------------------
__device__ __forceinline__ uint32_t smem_to_u32(const void* p) {
    uint32_t a;
    asm("{ .reg .u64 t; cvta.to.shared.u64 t, %1; cvt.u32.u64 %0, t; }" : "=r"(a) : "l"(p));
    return a;
}

#define CP_ASYNC16(smem_u32, gptr) \
    asm volatile("cp.async.cg.shared.global [%0], [%1], 16;" :: "r"(smem_u32), "l"(gptr) : "memory")
#define CP_ASYNC_COMMIT() asm volatile("cp.async.commit_group;" ::: "memory")
#define CP_ASYNC_WAIT0()  asm volatile("cp.async.wait_group 0;" ::: "memory")
#define CP_ASYNC_WAIT1()  asm volatile("cp.async.wait_group 1;" ::: "memory")

__device__ __forceinline__ void ldsm_x4(uint32_t* r, uint32_t addr) {
    asm volatile("ldmatrix.sync.aligned.m8n8.x4.shared.b16 {%0,%1,%2,%3}, [%4];"
        : "=r"(r[0]), "=r"(r[1]), "=r"(r[2]), "=r"(r[3]) : "r"(addr));
}

__device__ __forceinline__ void mma16816(float* c, const uint32_t* a, const uint32_t* b) {
    asm volatile(
        "mma.sync.aligned.m16n8k16.row.col.f32.f16.f16.f32 "
        "{%0,%1,%2,%3}, {%4,%5,%6,%7}, {%8,%9}, {%0,%1,%2,%3};"
        : "+f"(c[0]), "+f"(c[1]), "+f"(c[2]), "+f"(c[3])
        : "r"(a[0]), "r"(a[1]), "r"(a[2]), "r"(a[3]), "r"(b[0]), "r"(b[1]));
}

// ---------------------------------------------------------------------------
// 3-term fp16-split GEMM:  C = alpha * (Ah+Al) @ (Bh+Bl)^T  (drop Al*Bl)
// A: [M,K] row-major (K contig), B: [N,K] row-major (K contig)
// mode 0: C0 fp32 [M,N] (+ z*sC);  mode 1: C0/C1 fp16 hi/lo [M,N];
// mode 2: C0/C1 fp16 hi/lo transposed as [b][E_][N_] (v-projection only).
// Block tile 128x128, BK=32, 8 warps (warp tile 64x32), double-buffered.
// ---------------------------------------------------------------------------
#define BKH 32              // K halves per slab
#define ROWH 40             // padded row length in halves (32 + 8)
#define TILE_BYTES (128 * ROWH * 2)      // 10240
#define STAGE_BYTES (4 * TILE_BYTES)     // 40960: Ah, Al, Bh, Bl
#define GEMM_SMEM_TOTAL (2 * STAGE_BYTES)

__global__ __launch_bounds__(256, 1) void gemm3t(
    const __half* __restrict__ Ah, const __half* __restrict__ Al,
    const __half* __restrict__ Bh, const __half* __restrict__ Bl,
    int M, int N, int K,
    long sA, long sB, long sC,
    float alpha, int mode,
    void* __restrict__ C0, void* __restrict__ C1)
{
    extern __shared__ char smem[];
    const uint32_t smem_base = smem_to_u32(smem);
    const int tid  = threadIdx.x;
    const int wid  = tid >> 5;
    const int lane = tid & 31;
    const int wm = wid & 1;        // 2 warps along M
    const int wn = wid >> 1;       // 4 warps along N
    const int z = blockIdx.z;

    Ah += (long)z * sA;  Al += (long)z * sA;
    Bh += (long)z * sB;  Bl += (long)z * sB;

    const int m0 = blockIdx.y * 128;
    const int n0 = blockIdx.x * 128;

    float acc[4][4][4];
    #pragma unroll
    for (int i = 0; i < 4; i++)
        #pragma unroll
        for (int j = 0; j < 4; j++)
            #pragma unroll
            for (int c = 0; c < 4; c++) acc[i][j][c] = 0.0f;

    const int nslab = K / BKH;

    // -------- async slab loader --------
    auto load_slab = [&](int s) {
        const long koff = (long)s * BKH;
        const uint32_t st = smem_base + (uint32_t)(s & 1) * STAGE_BYTES;
        const int r_lo = tid >> 2;          // 0..63
        const int c    = tid & 3;           // 16B chunk
        #pragma unroll
        for (int i = 0; i < 8; i++) {
            const int tile = i >> 1;
            const int r = ((i & 1) << 6) + r_lo;       // 0..127
            const uint32_t so = st + (uint32_t)tile * TILE_BYTES + (uint32_t)(r * 80 + c * 16);
            const __half* g;
            long go;
            if (tile < 2) go = (long)(m0 + r) * K + koff + c * 8;
            else          go = (long)(n0 + r) * K + koff + c * 8;
            g = (tile == 0) ? Ah : (tile == 1) ? Al : (tile == 2) ? Bh : Bl;
            CP_ASYNC16(so, g + go);
        }
    };

    load_slab(0);
    CP_ASYNC_COMMIT();

    for (int s = 0; s < nslab; s++) {
        if (s + 1 < nslab) {
            load_slab(s + 1);
            CP_ASYNC_COMMIT();
            CP_ASYNC_WAIT1();
        } else {
            CP_ASYNC_WAIT0();
        }
        __syncthreads();

        const uint32_t st = smem_base + (uint32_t)(s & 1) * STAGE_BYTES;
        #pragma unroll
        for (int k16 = 0; k16 < 2; k16++) {
            // ---- A fragments (hi/lo) ----
            uint32_t ra_h[4][4], ra_l[4][4];
            const int am = lane & 15;
            const int ac = (lane >> 4) << 3;
            #pragma unroll
            for (int mi = 0; mi < 4; mi++) {
                const uint32_t ao =
                    (uint32_t)((wm * 64 + mi * 16 + am) * ROWH + k16 * 16 + ac) * 2;
                ldsm_x4(ra_h[mi], st + ao);
                ldsm_x4(ra_l[mi], st + TILE_BYTES + ao);
            }
            // ---- B fragments (hi/lo) ----
            uint32_t rb_h[4][2], rb_l[4][2];
            const int bn = ((lane >> 4) << 3) + (lane & 7);
            const int bc = ((lane >> 3) & 1) << 3;
            #pragma unroll
            for (int pair = 0; pair < 2; pair++) {
                const uint32_t bo =
                    (uint32_t)((wn * 32 + pair * 16 + bn) * ROWH + k16 * 16 + bc) * 2;
                uint32_t t4[4];
                ldsm_x4(t4, st + 2 * TILE_BYTES + bo);
                rb_h[pair * 2][0] = t4[0]; rb_h[pair * 2][1] = t4[1];
                rb_h[pair * 2 + 1][0] = t4[2]; rb_h[pair * 2 + 1][1] = t4[3];
                ldsm_x4(t4, st + 3 * TILE_BYTES + bo);
                rb_l[pair * 2][0] = t4[0]; rb_l[pair * 2][1] = t4[1];
                rb_l[pair * 2 + 1][0] = t4[2]; rb_l[pair * 2 + 1][1] = t4[3];
            }
            // ---- MMAs: hi*hi + hi*lo + lo*hi ----
            #pragma unroll
            for (int mi = 0; mi < 4; mi++)
                #pragma unroll
                for (int ni = 0; ni < 4; ni++) {
                    mma16816(acc[mi][ni], ra_h[mi], rb_h[ni]);
                    mma16816(acc[mi][ni], ra_h[mi], rb_l[ni]);
                    mma16816(acc[mi][ni], ra_l[mi], rb_h[ni]);
                }
        }
        __syncthreads();
    }

    // -------- epilogue (register accumulators -> global) --------
    const int rq = lane >> 2;             // 0..7
    const int cq = (lane & 3) * 2;
    #pragma unroll
    for (int mi = 0; mi < 4; mi++) {
        #pragma unroll
        for (int ni = 0; ni < 4; ni++) {
            const int mA = m0 + wm * 64 + mi * 16 + rq;
            const int mB = mA + 8;
            const int n  = n0 + wn * 32 + ni * 8 + cq;
            const float v0 = acc[mi][ni][0] * alpha;
            const float v1 = acc[mi][ni][1] * alpha;
            const float v2 = acc[mi][ni][2] * alpha;
            const float v3 = acc[mi][ni][3] * alpha;
            if (mode == 0) {
                float* Cf = (float*)C0 + (size_t)z * sC;
                *(float2*)(Cf + (size_t)mA * N + n) = make_float2(v0, v1);
                *(float2*)(Cf + (size_t)mB * N + n) = make_float2(v2, v3);
            } else if (mode == 1) {
                __half h0 = __float2half_rn(v0), h1 = __float2half_rn(v1);
                __half h2 = __float2half_rn(v2), h3 = __float2half_rn(v3);
                __half l0 = __float2half_rn(v0 - __half2float(h0));
                __half l1 = __float2half_rn(v1 - __half2float(h1));
                __half l2 = __float2half_rn(v2 - __half2float(h2));
                __half l3 = __float2half_rn(v3 - __half2float(h3));
                *(__half2*)((__half*)C0 + (size_t)mA * N + n) = __halves2half2(h0, h1);
                *(__half2*)((__half*)C0 + (size_t)mB * N + n) = __halves2half2(h2, h3);
                *(__half2*)((__half*)C1 + (size_t)mA * N + n) = __halves2half2(l0, l1);
                *(__half2*)((__half*)C1 + (size_t)mB * N + n) = __halves2half2(l2, l3);
            } else {
                // transposed store: C[b][n][m_local] with m -> (b, nn)
                #pragma unroll
                for (int e = 0; e < 4; e++) {
                    const int m = (e < 2) ? mA : mB;
                    const int nn2 = n + (e & 1);
                    const float val = (e == 0) ? v0 : (e == 1) ? v1 : (e == 2) ? v2 : v3;
                    const int bi = m >> 11;
                    const int mm = m & (N_ - 1);
                    const __half h = __float2half_rn(val);
                    const __half l = __float2half_rn(val - __half2float(h));
                    const size_t idx = ((size_t)bi * E_ + nn2) * N_ + mm;
                    ((__half*)C0)[idx] = h;
                    ((__half*)C1)[idx] = l;
                }
            }
        }
    }
}

// ---------------------------------------------------------------------------
// fp32 -> (fp16 hi, fp16 lo) elementwise split
// ---------------------------------------------------------------------------
__device__ __forceinline__ void split_store4(__half* h, __half* l, size_t idx, float4 v) {
    const __half h0 = __float2half_rn(v.x);
    const __half h1 = __float2half_rn(v.y);
    const __half h2 = __float2half_rn(v.z);
    const __half h3 = __float2half_rn(v.w);
    const __half l0 = __float2half_rn(v.x - __half2float(h0));
    const __half l1 = __float2half_rn(v.y - __half2float(h1));
    const __half l2 = __float2half_rn(v.z - __half2float(h2));
    const __half l3 = __float2half_rn(v.w - __half2float(h3));
    __half2* hp = (__half2*)(h + idx);
    __half2* lp = (__half2*)(l + idx);
    hp[0] = __halves2half2(h0, h1);  hp[1] = __halves2half2(h2, h3);
    lp[0] = __halves2half2(l0, l1);  lp[1] = __halves2half2(l2, l3);
}

__global__ __launch_bounds__(256) void split_fp32(
    const float* __restrict__ x, __half* __restrict__ h,
    __half* __restrict__ l, long n4)
{
    for (long i = blockIdx.x * 256 + threadIdx.x; i < n4; i += (long)gridDim.x * 256) {
        float4 v = ((const float4*)x)[i];
        split_store4(h, l, (size_t)i * 4, v);
    }
}

// ---------------------------------------------------------------------------
// fused softmax (in place, fp32) + fp16 hi/lo emission. One block per row.
// ---------------------------------------------------------------------------
__global__ __launch_bounds__(256) void softmax_fused(
    float* __restrict__ attn, __half* __restrict__ ah, __half* __restrict__ al)
{
    const size_t row = blockIdx.x;
    float* p = attn + row * N_;
    const int t = threadIdx.x;
    __shared__ float red[8];

    float4 va = ((const float4*)p)[t];
    float4 vb = ((const float4*)p)[t + 256];

    float vmax = fmaxf(fmaxf(fmaxf(va.x, va.y), fmaxf(va.z, va.w)),
                       fmaxf(fmaxf(vb.x, vb.y), fmaxf(vb.z, vb.w)));
    #pragma unroll
    for (int o = 16; o > 0; o >>= 1) vmax = fmaxf(vmax, __shfl_xor_sync(0xFFFFFFFF, vmax, o));
    if ((t & 31) == 0) red[t >> 5] = vmax;
    __syncthreads();
    float m = fmaxf(fmaxf(fmaxf(red[0], red[1]), fmaxf(red[2], red[3])),
                    fmaxf(fmaxf(red[4], red[5]), fmaxf(red[6], red[7])));
    __syncthreads();

    va.x = __expf(va.x - m); va.y = __expf(va.y - m); va.z = __expf(va.z - m); va.w = __expf(va.w - m);
    vb.x = __expf(vb.x - m); vb.y = __expf(vb.y - m); vb.z = __expf(vb.z - m); vb.w = __expf(vb.w - m);

    float sum = va.x + va.y + va.z + va.w + vb.x + vb.y + vb.z + vb.w;
    #pragma unroll
    for (int o = 16; o > 0; o >>= 1) sum += __shfl_xor_sync(0xFFFFFFFF, sum, o);
    if ((t & 31) == 0) red[t >> 5] = sum;
    __syncthreads();
    const float inv = 1.0f / (red[0] + red[1] + red[2] + red[3] + red[4] + red[5] + red[6] + red[7]);

    va.x *= inv; va.y *= inv; va.z *= inv; va.w *= inv;
    vb.x *= inv; vb.y *= inv; vb.z *= inv; vb.w *= inv;

    ((float4*)p)[t]       = va;
    ((float4*)p)[t + 256] = vb;
    split_store4(ah, al, row * N_ + (size_t)t * 4,        va);
    split_store4(ah, al, row * N_ + 1024 + (size_t)t * 4, vb);
}

// ---------------------------------------------------------------------------
extern "C" void kernel_launch(void* const* d_in, const int* in_sizes, int n_in,
                              void* d_out, int out_size)
{
    const float* q  = (const float*)d_in[0];
    const float* k  = (const float*)d_in[1];
    const float* v  = (const float*)d_in[2];
    const float* Wq = (const float*)d_in[3];
    const float* Wk = (const float*)d_in[4];
    const float* Wv = (const float*)d_in[5];

    float* out  = (float*)d_out;                 // [B, N, E]
    float* attn = out + (long)B_ * N_ * E_;      // [B, N, N]

    static int configured = 0;
    cudaFuncSetAttribute(gemm3t, cudaFuncAttributeMaxDynamicSharedMemorySize, GEMM_SMEM_TOTAL);
    (void)configured;

    __half *qh, *ql, *kh, *kl, *vh, *vl;
    __half *Wqh, *Wql, *Wkh, *Wkl, *Wvh, *Wvl;
    __half *qph, *qpl, *kph, *kpl, *vpth, *vptl, *ah, *al;
    cudaGetSymbolAddress((void**)&qh, g_qh);   cudaGetSymbolAddress((void**)&ql, g_ql);
    cudaGetSymbolAddress((void**)&kh, g_kh);   cudaGetSymbolAddress((void**)&kl, g_kl);
    cudaGetSymbolAddress((void**)&vh, g_vh);   cudaGetSymbolAddress((void**)&vl, g_vl);
    cudaGetSymbolAddress((void**)&Wqh, g_Wqh); cudaGetSymbolAddress((void**)&Wql, g_Wql);
    cudaGetSymbolAddress((void**)&Wkh, g_Wkh); cudaGetSymbolAddress((void**)&Wkl, g_Wkl);
    cudaGetSymbolAddress((void**)&Wvh, g_Wvh); cudaGetSymbolAddress((void**)&Wvl, g_Wvl);
    cudaGetSymbolAddress((void**)&qph, g_qph); cudaGetSymbolAddress((void**)&qpl, g_qpl);
    cudaGetSymbolAddress((void**)&kph, g_kph); cudaGetSymbolAddress((void**)&kpl, g_kpl);
    cudaGetSymbolAddress((void**)&vpth, g_vpth); cudaGetSymbolAddress((void**)&vptl, g_vptl);
    cudaGetSymbolAddress((void**)&ah, g_ah);   cudaGetSymbolAddress((void**)&al, g_al);

    const float c_eq  = rsqrtf((float)D_);
    const float scale = rsqrtf((float)E_);

    // 1) split fp32 inputs into fp16 hi/lo
    split_fp32<<<2048, 256>>>(q,  qh, ql, QKV_ELEMS / 4);
    split_fp32<<<2048, 256>>>(k,  kh, kl, QKV_ELEMS / 4);
    split_fp32<<<2048, 256>>>(v,  vh, vl, QKV_ELEMS / 4);
    split_fp32<<<256, 256>>>(Wq, Wqh, Wql, W_ELEMS / 4);
    split_fp32<<<256, 256>>>(Wk, Wkh, Wkl, W_ELEMS / 4);
    split_fp32<<<256, 256>>>(Wv, Wvh, Wvl, W_ELEMS / 4);

    // 2) projections: [16384,512] @ W^T, alpha=c_eq
    {
        dim3 grid(E_ / 128, (B_ * N_) / 128, 1);
        gemm3t<<<grid, 256, GEMM_SMEM_TOTAL>>>(qh, ql, Wqh, Wql, B_ * N_, E_, D_,
                                               0, 0, 0, c_eq, 1, qph, qpl);
        gemm3t<<<grid, 256, GEMM_SMEM_TOTAL>>>(kh, kl, Wkh, Wkl, B_ * N_, E_, D_,
                                               0, 0, 0, c_eq, 1, kph, kpl);
        gemm3t<<<grid, 256, GEMM_SMEM_TOTAL>>>(vh, vl, Wvh, Wvl, B_ * N_, E_, D_,
                                               0, 0, 0, c_eq, 2, vpth, vptl);
    }

    // 3) dots = qp @ kp^T * scale -> attn region (fp32), batched
    {
        dim3 grid(N_ / 128, N_ / 128, B_);
        gemm3t<<<grid, 256, GEMM_SMEM_TOTAL>>>(qph, qpl, kph, kpl, N_, N_, E_,
                                               (long)N_ * E_, (long)N_ * E_, (long)N_ * N_,
                                               scale, 0, attn, nullptr);
    }

    // 4) softmax (in place) + fp16 hi/lo split of attn
    softmax_fused<<<B_ * N_, 256>>>(attn, ah, al);

    // 5) out = attn @ vp  (vp^T stored [b][e][n], K=N_=2048 contiguous)
    {
        dim3 grid(E_ / 128, N_ / 128, B_);
        gemm3t<<<grid, 256, GEMM_SMEM_TOTAL>>>(ah, al, vpth, vptl, N_, E_, N_,
                                               (long)N_ * N_, (long)E_ * N_, (long)N_ * E_,
                                               1.0f, 0, out, nullptr);
    }
}

// round 4
// speedup vs baseline: 2.6475x; 1.1386x over previous
#include <cuda_runtime.h>
#include <cuda_fp16.h>
#include <cstdint>
#include <math.h>

// Problem constants
#define B_ 8
#define N_ 2048
#define D_ 512
#define E_ 512

static constexpr long QKV_ELEMS  = (long)B_ * N_ * D_;   // 8,388,608
static constexpr long W_ELEMS    = (long)E_ * D_;        // 262,144
static constexpr long ATTN_ELEMS = (long)B_ * N_ * N_;   // 33,554,432

// ---------------- scratch (static device arrays; allocation-guard safe) ----
__device__ __half g_qh[QKV_ELEMS],  g_ql[QKV_ELEMS];
__device__ __half g_kh[QKV_ELEMS],  g_kl[QKV_ELEMS];
__device__ __half g_vh[QKV_ELEMS],  g_vl[QKV_ELEMS];
__device__ __half g_Wqh[W_ELEMS],   g_Wql[W_ELEMS];
__device__ __half g_Wkh[W_ELEMS],   g_Wkl[W_ELEMS];
__device__ __half g_Wvh[W_ELEMS],   g_Wvl[W_ELEMS];
__device__ __half g_qph[QKV_ELEMS], g_qpl[QKV_ELEMS];
__device__ __half g_kph[QKV_ELEMS], g_kpl[QKV_ELEMS];
__device__ __half g_vpth[QKV_ELEMS], g_vptl[QKV_ELEMS];   // transposed [b][e][n]
__device__ __half g_ah[ATTN_ELEMS], g_al[ATTN_ELEMS];

// ---------------- PTX helpers ----------------------------------------------
__device__ __forceinline__ uint32_t smem_to_u32(const void* p) {
    uint32_t a;
    asm("{ .reg .u64 t; cvta.to.shared.u64 t, %1; cvt.u32.u64 %0, t; }" : "=r"(a) : "l"(p));
    return a;
}

#define CP_ASYNC16(smem_u32, gptr) \
    asm volatile("cp.async.cg.shared.global [%0], [%1], 16;" :: "r"(smem_u32), "l"(gptr) : "memory")
#define CP_ASYNC_COMMIT() asm volatile("cp.async.commit_group;" ::: "memory")
#define CP_ASYNC_WAIT1()  asm volatile("cp.async.wait_group 1;" ::: "memory")

__device__ __forceinline__ void ldsm_x4(uint32_t* r, uint32_t addr) {
    asm volatile("ldmatrix.sync.aligned.m8n8.x4.shared.b16 {%0,%1,%2,%3}, [%4];"
        : "=r"(r[0]), "=r"(r[1]), "=r"(r[2]), "=r"(r[3]) : "r"(addr));
}

__device__ __forceinline__ void mma16816(float* c, const uint32_t* a, const uint32_t* b) {
    asm volatile(
        "mma.sync.aligned.m16n8k16.row.col.f32.f16.f16.f32 "
        "{%0,%1,%2,%3}, {%4,%5,%6,%7}, {%8,%9}, {%0,%1,%2,%3};"
        : "+f"(c[0]), "+f"(c[1]), "+f"(c[2]), "+f"(c[3])
        : "r"(a[0]), "r"(a[1]), "r"(a[2]), "r"(a[3]), "r"(b[0]), "r"(b[1]));
}

// ---------------------------------------------------------------------------
// 3-term fp16-split GEMM:  C = alpha * (Ah+Al) @ (Bh+Bl)^T  (drop Al*Bl)
// A: [M,K] row-major (K contig), B: [N,K] row-major (K contig)
// mode 0: C0 fp32 [M,N] (+ z*sC);  mode 1: C0/C1 fp16 hi/lo [M,N];
// mode 2: C0/C1 fp16 hi/lo transposed as [b][E_][N_] (v-projection only).
// Block tile 128x256, BK=32, 8 warps (warp tile 64x64), 3-stage cp.async ring.
// ---------------------------------------------------------------------------
#define BKH 32                              // K halves per slab
#define ROWH 40                             // padded row length in halves
#define ROWB 80                             // row bytes
#define A_TILE_B (128 * ROWB)               // 10240
#define B_TILE_B (256 * ROWB)               // 20480
#define STAGE_B (2 * A_TILE_B + 2 * B_TILE_B)   // 61440: Ah, Al, Bh, Bl
#define OFF_AL (A_TILE_B)
#define OFF_BH (2 * A_TILE_B)
#define OFF_BL (2 * A_TILE_B + B_TILE_B)
#define NSTAGE 3
#define GEMM_SMEM_TOTAL (NSTAGE * STAGE_B)  // 184320

__global__ __launch_bounds__(256, 1) void gemm3t(
    const __half* __restrict__ Ah, const __half* __restrict__ Al,
    const __half* __restrict__ Bh, const __half* __restrict__ Bl,
    int M, int N, int K,
    long sA, long sB, long sC,
    float alpha, int mode,
    void* __restrict__ C0, void* __restrict__ C1)
{
    extern __shared__ char smem[];
    const uint32_t smem_base = smem_to_u32(smem);
    const int tid  = threadIdx.x;
    const int wid  = tid >> 5;
    const int lane = tid & 31;
    const int wm = wid & 1;        // 2 warps along M (64 rows each)
    const int wn = wid >> 1;       // 4 warps along N (64 cols each)
    const int z = blockIdx.z;

    Ah += (long)z * sA;  Al += (long)z * sA;
    Bh += (long)z * sB;  Bl += (long)z * sB;

    const int m0 = blockIdx.y * 128;
    const int n0 = blockIdx.x * 256;

    float acc[4][8][4];
    #pragma unroll
    for (int i = 0; i < 4; i++)
        #pragma unroll
        for (int j = 0; j < 8; j++)
            #pragma unroll
            for (int c = 0; c < 4; c++) acc[i][j][c] = 0.0f;

    const int nslab = K / BKH;

    const int lrow = tid >> 2;        // 0..63
    const int lch  = tid & 3;         // 16B chunk (8 halves)

    // -------- async slab loader: 12 cp.async per thread --------
    auto load_slab = [&](int s) {
        const long koff = (long)s * BKH + lch * 8;
        const uint32_t st = smem_base + (uint32_t)(s % NSTAGE) * STAGE_B;
        const uint32_t so = (uint32_t)(lrow * ROWB + lch * 16);
        #pragma unroll
        for (int i = 0; i < 2; i++) {      // A: 128 rows
            const int r = lrow + 64 * i;
            const long g = (long)(m0 + r) * K + koff;
            CP_ASYNC16(st +          so + i * (64 * ROWB), Ah + g);
            CP_ASYNC16(st + OFF_AL + so + i * (64 * ROWB), Al + g);
        }
        #pragma unroll
        for (int i = 0; i < 4; i++) {      // B: 256 rows
            const int r = lrow + 64 * i;
            const long g = (long)(n0 + r) * K + koff;
            CP_ASYNC16(st + OFF_BH + so + i * (64 * ROWB), Bh + g);
            CP_ASYNC16(st + OFF_BL + so + i * (64 * ROWB), Bl + g);
        }
    };

    load_slab(0); CP_ASYNC_COMMIT();
    if (nslab > 1) load_slab(1);
    CP_ASYNC_COMMIT();

    const int am = lane & 15;
    const int ac = (lane >> 4) << 3;
    const int bn = ((lane >> 4) << 3) + (lane & 7);
    const int bc = ((lane >> 3) & 1) << 3;

    for (int s = 0; s < nslab; s++) {
        CP_ASYNC_WAIT1();          // slab s resident (only s+1 may be pending)
        __syncthreads();           // all warps past previous consume + see data

        if (s + 2 < nslab) load_slab(s + 2);
        CP_ASYNC_COMMIT();         // keep group numbering (empty group ok)

        const uint32_t st = smem_base + (uint32_t)(s % NSTAGE) * STAGE_B;
        #pragma unroll
        for (int k16 = 0; k16 < 2; k16++) {
            // ---- A fragments (hi/lo): 8 ldsm.x4 ----
            uint32_t ra_h[4][4], ra_l[4][4];
            #pragma unroll
            for (int mi = 0; mi < 4; mi++) {
                const uint32_t ao =
                    (uint32_t)((wm * 64 + mi * 16 + am) * ROWH + k16 * 16 + ac) * 2;
                ldsm_x4(ra_h[mi], st + ao);
                ldsm_x4(ra_l[mi], st + OFF_AL + ao);
            }
            // ---- B pairs: 2 ldsm.x4 + 24 MMAs per pair ----
            #pragma unroll
            for (int pair = 0; pair < 4; pair++) {
                const uint32_t bo =
                    (uint32_t)((wn * 64 + pair * 16 + bn) * ROWH + k16 * 16 + bc) * 2;
                uint32_t th[4], tl[4];
                ldsm_x4(th, st + OFF_BH + bo);
                ldsm_x4(tl, st + OFF_BL + bo);
                #pragma unroll
                for (int nj = 0; nj < 2; nj++) {
                    const uint32_t bh2[2] = { th[nj * 2], th[nj * 2 + 1] };
                    const uint32_t bl2[2] = { tl[nj * 2], tl[nj * 2 + 1] };
                    #pragma unroll
                    for (int mi = 0; mi < 4; mi++) {
                        float* a = acc[mi][pair * 2 + nj];
                        mma16816(a, ra_h[mi], bh2);
                        mma16816(a, ra_h[mi], bl2);
                        mma16816(a, ra_l[mi], bh2);
                    }
                }
            }
        }
    }

    // -------- epilogue (register accumulators -> global) --------
    const int rq = lane >> 2;             // 0..7
    const int cq = (lane & 3) * 2;
    #pragma unroll
    for (int mi = 0; mi < 4; mi++) {
        #pragma unroll
        for (int ni = 0; ni < 8; ni++) {
            const int mA = m0 + wm * 64 + mi * 16 + rq;
            const int mB = mA + 8;
            const int n  = n0 + wn * 64 + ni * 8 + cq;
            const float v0 = acc[mi][ni][0] * alpha;
            const float v1 = acc[mi][ni][1] * alpha;
            const float v2 = acc[mi][ni][2] * alpha;
            const float v3 = acc[mi][ni][3] * alpha;
            if (mode == 0) {
                float* Cf = (float*)C0 + (size_t)z * sC;
                *(float2*)(Cf + (size_t)mA * N + n) = make_float2(v0, v1);
                *(float2*)(Cf + (size_t)mB * N + n) = make_float2(v2, v3);
            } else if (mode == 1) {
                __half h0 = __float2half_rn(v0), h1 = __float2half_rn(v1);
                __half h2 = __float2half_rn(v2), h3 = __float2half_rn(v3);
                __half l0 = __float2half_rn(v0 - __half2float(h0));
                __half l1 = __float2half_rn(v1 - __half2float(h1));
                __half l2 = __float2half_rn(v2 - __half2float(h2));
                __half l3 = __float2half_rn(v3 - __half2float(h3));
                *(__half2*)((__half*)C0 + (size_t)mA * N + n) = __halves2half2(h0, h1);
                *(__half2*)((__half*)C0 + (size_t)mB * N + n) = __halves2half2(h2, h3);
                *(__half2*)((__half*)C1 + (size_t)mA * N + n) = __halves2half2(l0, l1);
                *(__half2*)((__half*)C1 + (size_t)mB * N + n) = __halves2half2(l2, l3);
            } else {
                // transposed store: C[b][e][n] with m -> (b, nn)
                #pragma unroll
                for (int e = 0; e < 4; e++) {
                    const int m = (e < 2) ? mA : mB;
                    const int nn2 = n + (e & 1);
                    const float val = (e == 0) ? v0 : (e == 1) ? v1 : (e == 2) ? v2 : v3;
                    const int bi = m >> 11;
                    const int mm = m & (N_ - 1);
                    const __half h = __float2half_rn(val);
                    const __half l = __float2half_rn(val - __half2float(h));
                    const size_t idx = ((size_t)bi * E_ + nn2) * N_ + mm;
                    ((__half*)C0)[idx] = h;
                    ((__half*)C1)[idx] = l;
                }
            }
        }
    }
}

// ---------------------------------------------------------------------------
// fp32 -> (fp16 hi, fp16 lo) elementwise split
// ---------------------------------------------------------------------------
__device__ __forceinline__ void split_store4(__half* h, __half* l, size_t idx, float4 v) {
    const __half h0 = __float2half_rn(v.x);
    const __half h1 = __float2half_rn(v.y);
    const __half h2 = __float2half_rn(v.z);
    const __half h3 = __float2half_rn(v.w);
    const __half l0 = __float2half_rn(v.x - __half2float(h0));
    const __half l1 = __float2half_rn(v.y - __half2float(h1));
    const __half l2 = __float2half_rn(v.z - __half2float(h2));
    const __half l3 = __float2half_rn(v.w - __half2float(h3));
    __half2* hp = (__half2*)(h + idx);
    __half2* lp = (__half2*)(l + idx);
    hp[0] = __halves2half2(h0, h1);  hp[1] = __halves2half2(h2, h3);
    lp[0] = __halves2half2(l0, l1);  lp[1] = __halves2half2(l2, l3);
}

__global__ __launch_bounds__(256) void split_fp32(
    const float* __restrict__ x, __half* __restrict__ h,
    __half* __restrict__ l, long n4)
{
    for (long i = blockIdx.x * 256 + threadIdx.x; i < n4; i += (long)gridDim.x * 256) {
        float4 v = ((const float4*)x)[i];
        split_store4(h, l, (size_t)i * 4, v);
    }
}

// ---------------------------------------------------------------------------
// fused softmax (in place, fp32) + fp16 hi/lo emission. One block per row.
// ---------------------------------------------------------------------------
__global__ __launch_bounds__(256) void softmax_fused(
    float* __restrict__ attn, __half* __restrict__ ah, __half* __restrict__ al)
{
    const size_t row = blockIdx.x;
    float* p = attn + row * N_;
    const int t = threadIdx.x;
    __shared__ float red[8];

    float4 va = ((const float4*)p)[t];
    float4 vb = ((const float4*)p)[t + 256];

    float vmax = fmaxf(fmaxf(fmaxf(va.x, va.y), fmaxf(va.z, va.w)),
                       fmaxf(fmaxf(vb.x, vb.y), fmaxf(vb.z, vb.w)));
    #pragma unroll
    for (int o = 16; o > 0; o >>= 1) vmax = fmaxf(vmax, __shfl_xor_sync(0xFFFFFFFF, vmax, o));
    if ((t & 31) == 0) red[t >> 5] = vmax;
    __syncthreads();
    float m = fmaxf(fmaxf(fmaxf(red[0], red[1]), fmaxf(red[2], red[3])),
                    fmaxf(fmaxf(red[4], red[5]), fmaxf(red[6], red[7])));
    __syncthreads();

    va.x = __expf(va.x - m); va.y = __expf(va.y - m); va.z = __expf(va.z - m); va.w = __expf(va.w - m);
    vb.x = __expf(vb.x - m); vb.y = __expf(vb.y - m); vb.z = __expf(vb.z - m); vb.w = __expf(vb.w - m);

    float sum = va.x + va.y + va.z + va.w + vb.x + vb.y + vb.z + vb.w;
    #pragma unroll
    for (int o = 16; o > 0; o >>= 1) sum += __shfl_xor_sync(0xFFFFFFFF, sum, o);
    if ((t & 31) == 0) red[t >> 5] = sum;
    __syncthreads();
    const float inv = 1.0f / (red[0] + red[1] + red[2] + red[3] + red[4] + red[5] + red[6] + red[7]);

    va.x *= inv; va.y *= inv; va.z *= inv; va.w *= inv;
    vb.x *= inv; vb.y *= inv; vb.z *= inv; vb.w *= inv;

    ((float4*)p)[t]       = va;
    ((float4*)p)[t + 256] = vb;
    split_store4(ah, al, row * N_ + (size_t)t * 4,        va);
    split_store4(ah, al, row * N_ + 1024 + (size_t)t * 4, vb);
}

// ---------------------------------------------------------------------------
extern "C" void kernel_launch(void* const* d_in, const int* in_sizes, int n_in,
                              void* d_out, int out_size)
{
    const float* q  = (const float*)d_in[0];
    const float* k  = (const float*)d_in[1];
    const float* v  = (const float*)d_in[2];
    const float* Wq = (const float*)d_in[3];
    const float* Wk = (const float*)d_in[4];
    const float* Wv = (const float*)d_in[5];

    float* out  = (float*)d_out;                 // [B, N, E]
    float* attn = out + (long)B_ * N_ * E_;      // [B, N, N]

    cudaFuncSetAttribute(gemm3t, cudaFuncAttributeMaxDynamicSharedMemorySize, GEMM_SMEM_TOTAL);

    __half *qh, *ql, *kh, *kl, *vh, *vl;
    __half *Wqh, *Wql, *Wkh, *Wkl, *Wvh, *Wvl;
    __half *qph, *qpl, *kph, *kpl, *vpth, *vptl, *ah, *al;
    cudaGetSymbolAddress((void**)&qh, g_qh);   cudaGetSymbolAddress((void**)&ql, g_ql);
    cudaGetSymbolAddress((void**)&kh, g_kh);   cudaGetSymbolAddress((void**)&kl, g_kl);
    cudaGetSymbolAddress((void**)&vh, g_vh);   cudaGetSymbolAddress((void**)&vl, g_vl);
    cudaGetSymbolAddress((void**)&Wqh, g_Wqh); cudaGetSymbolAddress((void**)&Wql, g_Wql);
    cudaGetSymbolAddress((void**)&Wkh, g_Wkh); cudaGetSymbolAddress((void**)&Wkl, g_Wkl);
    cudaGetSymbolAddress((void**)&Wvh, g_Wvh); cudaGetSymbolAddress((void**)&Wvl, g_Wvl);
    cudaGetSymbolAddress((void**)&qph, g_qph); cudaGetSymbolAddress((void**)&qpl, g_qpl);
    cudaGetSymbolAddress((void**)&kph, g_kph); cudaGetSymbolAddress((void**)&kpl, g_kpl);
    cudaGetSymbolAddress((void**)&vpth, g_vpth); cudaGetSymbolAddress((void**)&vptl, g_vptl);
    cudaGetSymbolAddress((void**)&ah, g_ah);   cudaGetSymbolAddress((void**)&al, g_al);

    const float c_eq  = rsqrtf((float)D_);
    const float scale = rsqrtf((float)E_);

    // 1) split fp32 inputs into fp16 hi/lo
    split_fp32<<<2048, 256>>>(q,  qh, ql, QKV_ELEMS / 4);
    split_fp32<<<2048, 256>>>(k,  kh, kl, QKV_ELEMS / 4);
    split_fp32<<<2048, 256>>>(v,  vh, vl, QKV_ELEMS / 4);
    split_fp32<<<256, 256>>>(Wq, Wqh, Wql, W_ELEMS / 4);
    split_fp32<<<256, 256>>>(Wk, Wkh, Wkl, W_ELEMS / 4);
    split_fp32<<<256, 256>>>(Wv, Wvh, Wvl, W_ELEMS / 4);

    // 2) projections: [16384,512] @ W^T, alpha=c_eq
    {
        dim3 grid(E_ / 256, (B_ * N_) / 128, 1);
        gemm3t<<<grid, 256, GEMM_SMEM_TOTAL>>>(qh, ql, Wqh, Wql, B_ * N_, E_, D_,
                                               0, 0, 0, c_eq, 1, qph, qpl);
        gemm3t<<<grid, 256, GEMM_SMEM_TOTAL>>>(kh, kl, Wkh, Wkl, B_ * N_, E_, D_,
                                               0, 0, 0, c_eq, 1, kph, kpl);
        gemm3t<<<grid, 256, GEMM_SMEM_TOTAL>>>(vh, vl, Wvh, Wvl, B_ * N_, E_, D_,
                                               0, 0, 0, c_eq, 2, vpth, vptl);
    }

    // 3) dots = qp @ kp^T * scale -> attn region (fp32), batched
    {
        dim3 grid(N_ / 256, N_ / 128, B_);
        gemm3t<<<grid, 256, GEMM_SMEM_TOTAL>>>(qph, qpl, kph, kpl, N_, N_, E_,
                                               (long)N_ * E_, (long)N_ * E_, (long)N_ * N_,
                                               scale, 0, attn, nullptr);
    }

    // 4) softmax (in place) + fp16 hi/lo split of attn
    softmax_fused<<<B_ * N_, 256>>>(attn, ah, al);

    // 5) out = attn @ vp  (vp^T stored [b][e][n], K=N_=2048 contiguous)
    {
        dim3 grid(E_ / 256, N_ / 128, B_);
        gemm3t<<<grid, 256, GEMM_SMEM_TOTAL>>>(ah, al, vpth, vptl, N_, E_, N_,
                                               (long)N_ * N_, (long)E_ * N_, (long)N_ * E_,
                                               1.0f, 0, out, nullptr);
    }
}